// round 9
// baseline (speedup 1.0000x reference)
#include <cuda_runtime.h>
#include <cuda_bf16.h>
#include <cstdint>
#include <cstddef>
#include <math.h>

// Problem constants
#define B_    2
#define CDIM  256
#define NTOK  32768          // 32*32*32 tokens
#define HEADS 8
#define DH    32
#define O1    768            // 3 * HEADS * DH

// GEMM tiling
#define BM 128
#define BN 128
#define BK 32
#define APITCH 40            // 32 + 8 bf16 pad  (80B rows -> conflict-free ldmatrix)
#define BPITCH 136           // 128 + 8 bf16 pad (272B rows -> conflict-free ldmatrix.trans)
#define OA_H 0
#define OA_L (BM*APITCH)                 // 5120
#define OB_H (2*BM*APITCH)               // 10240
#define OB_L (2*BM*APITCH + BK*BPITCH)   // 14592
#define BUFE (2*BM*APITCH + 2*BK*BPITCH) // 18944 bf16 elems per stage
#define GEMM_SMEM (2*BUFE*2)             // bytes (double buffered) = 75776
#define EPI_PITCH 129                    // fp32 epilogue scratch pitch

// ---------------------------------------------------------------------------
// Scratch (device globals; no cudaMalloc allowed)
// ---------------------------------------------------------------------------
__device__ float g_qkv[(size_t)B_ * O1 * NTOK];                 // q(unused) | exp(k) | v, fp32
__device__ float g_ksum[B_ * 256];
__device__ float g_ksum_part[B_ * 256 * 256];                    // [b][krow][ntile]
__device__ float g_ctx_part[(size_t)B_ * HEADS * 256 * DH * DH];
__device__ float g_ctx[B_ * HEADS * DH * DH];
__device__ __align__(16) __nv_bfloat16 g_xh[(size_t)B_*CDIM*NTOK];
__device__ __align__(16) __nv_bfloat16 g_xl[(size_t)B_*CDIM*NTOK];
__device__ __align__(16) __nv_bfloat16 g_qh[(size_t)B_*CDIM*NTOK];
__device__ __align__(16) __nv_bfloat16 g_ql[(size_t)B_*CDIM*NTOK];
__device__ __align__(16) __nv_bfloat16 g_wh[O1*CDIM];
__device__ __align__(16) __nv_bfloat16 g_wl[O1*CDIM];
__device__ __align__(16) __nv_bfloat16 g_w2h[B_*CDIM*CDIM];
__device__ __align__(16) __nv_bfloat16 g_w2l[B_*CDIM*CDIM];

// ---------------------------------------------------------------------------
// PTX helpers
// ---------------------------------------------------------------------------
#define CP16(dst, src) \
    asm volatile("cp.async.cg.shared.global [%0], [%1], 16;" :: "r"(dst), "l"(src) : "memory")
#define CP_COMMIT() asm volatile("cp.async.commit_group;" ::: "memory")
#define CP_WAIT0()  asm volatile("cp.async.wait_group 0;"  ::: "memory")

#define LDSM4(r0,r1,r2,r3,a) \
    asm volatile("ldmatrix.sync.aligned.m8n8.x4.shared.b16 {%0,%1,%2,%3}, [%4];" \
                 : "=r"(r0),"=r"(r1),"=r"(r2),"=r"(r3) : "r"(a))
#define LDSM4T(r0,r1,r2,r3,a) \
    asm volatile("ldmatrix.sync.aligned.m8n8.x4.trans.shared.b16 {%0,%1,%2,%3}, [%4];" \
                 : "=r"(r0),"=r"(r1),"=r"(r2),"=r"(r3) : "r"(a))

#define MMA3(d, a, b) \
    asm volatile("mma.sync.aligned.m16n8k16.row.col.f32.bf16.bf16.f32 " \
                 "{%0,%1,%2,%3},{%4,%5,%6,%7},{%8,%9},{%0,%1,%2,%3};" \
                 : "+f"((d)[0]),"+f"((d)[1]),"+f"((d)[2]),"+f"((d)[3]) \
                 : "r"((a)[0]),"r"((a)[1]),"r"((a)[2]),"r"((a)[3]), \
                   "r"((b)[0]),"r"((b)[1]))

// ---------------------------------------------------------------------------
// Split-bf16 tensor-core GEMM with optional fused qkv epilogue.
// C[M,N] = A[M,K] * B[K,N]; A,B as (hi,lo) bf16 pairs, 3-term split.
// GRID: (m_tiles, n_tiles, batch) — m fastest-varying so that one scheduling
// wave covers all m-tiles of the same n-columns: B tiles hit L2 instead of DRAM.
// FUSE_QKV: blockIdx.x 0-1 -> q softmax -> g_qh/g_ql bf16;
//           blockIdx.x 2-3 -> exp(k) -> C fp32 + partial row sums;
//           blockIdx.x 4-5 -> plain fp32 store (v).
// ---------------------------------------------------------------------------
template <bool FUSE_QKV>
__global__ __launch_bounds__(256, 2)
void gemm_bf16split(const __nv_bfloat16* __restrict__ Ah, const __nv_bfloat16* __restrict__ Al,
                    const __nv_bfloat16* __restrict__ Bh, const __nv_bfloat16* __restrict__ Bl,
                    float* __restrict__ C, int K, int N,
                    long sA, long sB, long sC)
{
    extern __shared__ __nv_bfloat16 smbuf[];
    const int bz = blockIdx.z;
    Ah += bz * sA;  Al += bz * sA;
    Bh += bz * sB;  Bl += bz * sB;
    C  += bz * sC;

    const int tid   = threadIdx.x;
    const int lane  = tid & 31;
    const int wid   = tid >> 5;
    const int warp_m = wid >> 2;       // 0..1 -> 64-row slab
    const int warp_n = wid & 3;        // 0..3 -> 32-col slab
    const int bm = blockIdx.x * BM;    // m fastest-varying (L2 reuse of B)
    const int bn = blockIdx.y * BN;

    const uint32_t su = (uint32_t)__cvta_generic_to_shared(smbuf);

    const int rowA = (lane & 7) + ((lane >> 3) & 1) * 8;
    const int colA = (lane >> 4) * 8;
    const uint32_t aOff = (uint32_t)(((warp_m * 64 + rowA) * APITCH + colA) * 2);
    const int rowB = (lane & 7) + ((lane >> 3) & 1) * 8;
    const int colB = warp_n * 32 + ((lane >> 4) & 1) * 8;
    const uint32_t bOff = (uint32_t)((rowB * BPITCH + colB) * 2);

    float acc[4][4][4];
#pragma unroll
    for (int i = 0; i < 4; i++)
#pragma unroll
        for (int j = 0; j < 4; j++)
#pragma unroll
            for (int r = 0; r < 4; r++) acc[i][j][r] = 0.f;

#define LOAD_HALF(buf, kt, id) do {                                                  \
    int ra = (id) >> 2, ca = ((id) & 3) * 8;                                         \
    uint32_t dA = su + (uint32_t)(((buf)*BUFE + ra*APITCH + ca) * 2);                \
    CP16(dA + OA_H*2, Ah + (long)(bm + ra) * K + (kt) + ca);                         \
    CP16(dA + OA_L*2, Al + (long)(bm + ra) * K + (kt) + ca);                         \
    int rb = (id) >> 4, cb = ((id) & 15) * 8;                                        \
    uint32_t dB = su + (uint32_t)(((buf)*BUFE + rb*BPITCH + cb) * 2);                \
    CP16(dB + OB_H*2, Bh + (long)((kt) + rb) * N + bn + cb);                         \
    CP16(dB + OB_L*2, Bl + (long)((kt) + rb) * N + bn + cb);                         \
} while (0)

#define LOAD_TILE(buf, kt) do {                                                      \
    LOAD_HALF(buf, kt, tid);                                                         \
    LOAD_HALF(buf, kt, tid + 256);                                                   \
    CP_COMMIT();                                                                     \
} while (0)

    LOAD_TILE(0, 0);
    CP_WAIT0();
    __syncthreads();

    int buf = 0;
    for (int kt = BK; kt <= K; kt += BK) {
        if (kt < K) LOAD_TILE(buf ^ 1, kt);

        const uint32_t stage = su + (uint32_t)(buf * BUFE * 2);
#pragma unroll
        for (int kk = 0; kk < BK; kk += 16) {
            uint32_t fbh[4][2], fbl[4][2];
#pragma unroll
            for (int pr = 0; pr < 2; pr++) {
                uint32_t adH = stage + (uint32_t)(OB_H*2) + (uint32_t)(kk*BPITCH*2) + bOff + (uint32_t)(pr*32);
                LDSM4T(fbh[2*pr][0], fbh[2*pr][1], fbh[2*pr+1][0], fbh[2*pr+1][1], adH);
                uint32_t adL = stage + (uint32_t)(OB_L*2) + (uint32_t)(kk*BPITCH*2) + bOff + (uint32_t)(pr*32);
                LDSM4T(fbl[2*pr][0], fbl[2*pr][1], fbl[2*pr+1][0], fbl[2*pr+1][1], adL);
            }
#pragma unroll
            for (int mt = 0; mt < 4; mt++) {
                uint32_t fah[4], fal[4];
                uint32_t aaH = stage + (uint32_t)(OA_H*2) + aOff + (uint32_t)((mt*16*APITCH + kk) * 2);
                LDSM4(fah[0], fah[1], fah[2], fah[3], aaH);
                uint32_t aaL = stage + (uint32_t)(OA_L*2) + aOff + (uint32_t)((mt*16*APITCH + kk) * 2);
                LDSM4(fal[0], fal[1], fal[2], fal[3], aaL);
#pragma unroll
                for (int nt = 0; nt < 4; nt++) {
                    MMA3(acc[mt][nt], fah, fbh[nt]);
                    MMA3(acc[mt][nt], fah, fbl[nt]);
                    MMA3(acc[mt][nt], fal, fbh[nt]);
                }
            }
        }

        if (kt < K) {
            CP_WAIT0();
            __syncthreads();
            buf ^= 1;
        }
    }
#undef LOAD_TILE
#undef LOAD_HALF

    const int r0 = warp_m * 64 + (lane >> 2);
    const int c0 = warp_n * 32 + (lane & 3) * 2;

    if (FUSE_QKV && blockIdx.x < 2) {
        // ---- q path: softmax over d (32 rows per head), write bf16 hi/lo ----
        __syncthreads();                      // main-loop smem reads done
        float* sf = (float*)smbuf;
#pragma unroll
        for (int mt = 0; mt < 4; mt++)
#pragma unroll
            for (int nt = 0; nt < 4; nt++) {
                int r = r0 + mt * 16, c = c0 + nt * 8;
                sf[r * EPI_PITCH + c]           = acc[mt][nt][0];
                sf[r * EPI_PITCH + c + 1]       = acc[mt][nt][1];
                sf[(r + 8) * EPI_PITCH + c]     = acc[mt][nt][2];
                sf[(r + 8) * EPI_PITCH + c + 1] = acc[mt][nt][3];
            }
        __syncthreads();

        const int col = tid & 127;
        const int h0  = tid >> 7;            // 0 or 1
        const long n  = bn + col;
#pragma unroll
        for (int hh = h0; hh < 4; hh += 2) {
            float v[DH];
            float mx = -1e30f;
#pragma unroll
            for (int d = 0; d < DH; d++) {
                v[d] = sf[(hh * DH + d) * EPI_PITCH + col];
                mx = fmaxf(mx, v[d]);
            }
            float s = 0.f;
#pragma unroll
            for (int d = 0; d < DH; d++) { v[d] = expf(v[d] - mx); s += v[d]; }
            float inv = 1.f / s;
            const int hglob = blockIdx.x * 4 + hh;
            __nv_bfloat16* qh = g_qh + ((long)bz * CDIM + hglob * DH) * NTOK + n;
            __nv_bfloat16* ql = g_ql + ((long)bz * CDIM + hglob * DH) * NTOK + n;
#pragma unroll
            for (int d = 0; d < DH; d++) {
                float q = v[d] * inv;
                __nv_bfloat16 hb = __float2bfloat16(q);
                qh[(long)d * NTOK] = hb;
                ql[(long)d * NTOK] = __float2bfloat16(q - __bfloat162float(hb));
            }
        }
    } else if (FUSE_QKV && blockIdx.x < 4) {
        // ---- k path: exp in regs -> gmem fp32 + smem; then partial row sums ----
        __syncthreads();
        float* sf = (float*)smbuf;
#pragma unroll
        for (int mt = 0; mt < 4; mt++)
#pragma unroll
            for (int nt = 0; nt < 4; nt++) {
                int r = r0 + mt * 16, c = c0 + nt * 8;
                float e0 = expf(acc[mt][nt][0]);
                float e1 = expf(acc[mt][nt][1]);
                float e2 = expf(acc[mt][nt][2]);
                float e3 = expf(acc[mt][nt][3]);
                float* cp = C + (long)(bm + r) * N + bn + c;
                *(float2*)cp               = make_float2(e0, e1);
                *(float2*)(cp + 8*(long)N) = make_float2(e2, e3);
                sf[r * EPI_PITCH + c]           = e0;
                sf[r * EPI_PITCH + c + 1]       = e1;
                sf[(r + 8) * EPI_PITCH + c]     = e2;
                sf[(r + 8) * EPI_PITCH + c + 1] = e3;
            }
        __syncthreads();
        if (tid < 128) {
            float s = 0.f;
#pragma unroll 8
            for (int c = 0; c < 128; c++) s += sf[tid * EPI_PITCH + c];
            int kr = (blockIdx.x - 2) * 128 + tid;   // 0..255
            g_ksum_part[((long)bz * 256 + kr) * 256 + blockIdx.y] = s;
        }
    } else {
        // ---- plain fp32 store (v tiles, and all of GEMM3) ----
#pragma unroll
        for (int mt = 0; mt < 4; mt++)
#pragma unroll
            for (int nt = 0; nt < 4; nt++) {
                long row = bm + r0 + mt * 16;
                float* cp = C + row * (long)N + bn + c0 + nt * 8;
                *(float2*)cp               = make_float2(acc[mt][nt][0], acc[mt][nt][1]);
                *(float2*)(cp + 8*(long)N) = make_float2(acc[mt][nt][2], acc[mt][nt][3]);
            }
    }
}

// ---------------------------------------------------------------------------
// fp32 -> (bf16 hi, bf16 lo) split conversion, 4 elems/thread.
// ---------------------------------------------------------------------------
__global__ void cvt_split(const float* __restrict__ src,
                          __nv_bfloat16* __restrict__ h, __nv_bfloat16* __restrict__ l,
                          long n)
{
    long i = ((long)blockIdx.x * blockDim.x + threadIdx.x) * 4;
    if (i >= n) return;
    float4 v = *(const float4*)(src + i);
    float a[4] = {v.x, v.y, v.z, v.w};
#pragma unroll
    for (int j = 0; j < 4; j++) {
        __nv_bfloat16 hh = __float2bfloat16(a[j]);
        h[i + j] = hh;
        l[i + j] = __float2bfloat16(a[j] - __bfloat162float(hh));
    }
}

// ---------------------------------------------------------------------------
// Reduce per-ntile partial k row sums: 256 -> 1 per (b, krow). Deterministic.
// ---------------------------------------------------------------------------
__global__ void ksum_reduce_kernel()
{
    int b  = blockIdx.x >> 8;
    int kr = blockIdx.x & 255;
    __shared__ float red[256];
    red[threadIdx.x] = g_ksum_part[((long)b * 256 + kr) * 256 + threadIdx.x];
    __syncthreads();
    for (int o = 128; o > 0; o >>= 1) {
        if (threadIdx.x < o) red[threadIdx.x] += red[threadIdx.x + o];
        __syncthreads();
    }
    if (threadIdx.x == 0) g_ksum[b * 256 + kr] = red[0];
}

// ---------------------------------------------------------------------------
// Partial contexts over 128-token stripes.
// ---------------------------------------------------------------------------
__global__ __launch_bounds__(128)
void ctx_part_kernel()
{
    const int chunk = blockIdx.x;        // 0..63 (512 tokens each)
    const int h     = blockIdx.y;
    const int b     = blockIdx.z;
    const int w     = threadIdx.x / 32;  // stripe within chunk (128 tokens)
    const int lane  = threadIdx.x % 32;

    __shared__ float ek_s[4][32][33];
    __shared__ float v_s [4][32][33];

    const long kbase = ((long)b * O1 + 256 + h * DH) * NTOK;
    const long vbase = ((long)b * O1 + 512 + h * DH) * NTOK;
    const int  n_base = chunk * 512 + w * 128;

    const int ti = lane / 4;
    const int tj = lane % 4;

    float acc[4][8];
#pragma unroll
    for (int i = 0; i < 4; i++)
#pragma unroll
        for (int j = 0; j < 8; j++) acc[i][j] = 0.f;

    for (int n0 = 0; n0 < 128; n0 += 32) {
#pragma unroll
        for (int p = 0; p < 8; p++) {
            int fl = p * 32 + lane;
            int d = fl / 8, nq = fl % 8;
            float4 ke = *(const float4*)(g_qkv + kbase + (long)d * NTOK + n_base + n0 + nq * 4);
            ek_s[w][nq * 4 + 0][d] = ke.x;
            ek_s[w][nq * 4 + 1][d] = ke.y;
            ek_s[w][nq * 4 + 2][d] = ke.z;
            ek_s[w][nq * 4 + 3][d] = ke.w;
            float4 ve = *(const float4*)(g_qkv + vbase + (long)d * NTOK + n_base + n0 + nq * 4);
            v_s[w][nq * 4 + 0][d] = ve.x;
            v_s[w][nq * 4 + 1][d] = ve.y;
            v_s[w][nq * 4 + 2][d] = ve.z;
            v_s[w][nq * 4 + 3][d] = ve.w;
        }
        __syncwarp();
#pragma unroll 8
        for (int n = 0; n < 32; n++) {
            float a[4], bb[8];
#pragma unroll
            for (int i = 0; i < 4; i++) a[i] = ek_s[w][n][ti * 4 + i];
#pragma unroll
            for (int j = 0; j < 8; j++) bb[j] = v_s[w][n][tj * 8 + j];
#pragma unroll
            for (int i = 0; i < 4; i++)
#pragma unroll
                for (int j = 0; j < 8; j++)
                    acc[i][j] = fmaf(a[i], bb[j], acc[i][j]);
        }
        __syncwarp();
    }

    const int stripe = chunk * 4 + w;    // 0..255
    float* out = g_ctx_part + ((long)(b * HEADS + h) * 256 + stripe) * (DH * DH);
#pragma unroll
    for (int i = 0; i < 4; i++)
#pragma unroll
        for (int j = 0; j < 8; j++)
            out[(ti * 4 + i) * DH + tj * 8 + j] = acc[i][j];
}

__global__ void ctx_reduce_kernel()
{
    int idx = blockIdx.x * blockDim.x + threadIdx.x;  // < B_*HEADS*1024
    int de = idx % (DH * DH);
    int bh = idx / (DH * DH);
    int d  = de / DH;
    int b  = bh / HEADS, h = bh % HEADS;
    const float* p = g_ctx_part + (long)bh * 256 * (DH * DH) + de;
    float s = 0.f;
#pragma unroll 8
    for (int st = 0; st < 256; st++) s += p[(long)st * (DH * DH)];
    float inv = 1.f / g_ksum[b * 256 + h * DH + d];
    g_ctx[(long)bh * (DH * DH) + de] = s * inv;
}

// ---------------------------------------------------------------------------
// Fold w_out with context; emit bf16 hi/lo W2.
// ---------------------------------------------------------------------------
__global__ void fold_w2_kernel(const float* __restrict__ w_out)
{
    int idx = blockIdx.x * blockDim.x + threadIdx.x;  // < B_*256*256
    int hd = idx % 256;
    int o  = (idx / 256) % 256;
    int b  = idx / 65536;
    int h = hd / DH, d = hd % DH;
    const float* wrow = w_out + o * 256 + h * DH;
    const float* ctx  = g_ctx + ((long)(b * HEADS + h) * DH + d) * DH;
    float s = 0.f;
#pragma unroll
    for (int e = 0; e < DH; e++) s = fmaf(wrow[e], ctx[e], s);
    __nv_bfloat16 hh = __float2bfloat16(s);
    g_w2h[(long)b * 65536 + o * 256 + hd] = hh;
    g_w2l[(long)b * 65536 + o * 256 + hd] = __float2bfloat16(s - __bfloat162float(hh));
}

// ---------------------------------------------------------------------------
// Launch
// ---------------------------------------------------------------------------
extern "C" void kernel_launch(void* const* d_in, const int* in_sizes, int n_in,
                              void* d_out, int out_size)
{
    const float* x     = (const float*)d_in[0];  // [2,256,32768]
    const float* w_qkv = (const float*)d_in[1];  // [768,256]
    const float* w_out = (const float*)d_in[2];  // [256,256]
    float* out = (float*)d_out;                  // [2,256,32768]

    float *qkv = nullptr;
    __nv_bfloat16 *xh, *xl, *qh, *ql, *wh, *wl, *w2h, *w2l;
    cudaGetSymbolAddress((void**)&qkv, g_qkv);
    cudaGetSymbolAddress((void**)&xh,  g_xh);
    cudaGetSymbolAddress((void**)&xl,  g_xl);
    cudaGetSymbolAddress((void**)&qh,  g_qh);
    cudaGetSymbolAddress((void**)&ql,  g_ql);
    cudaGetSymbolAddress((void**)&wh,  g_wh);
    cudaGetSymbolAddress((void**)&wl,  g_wl);
    cudaGetSymbolAddress((void**)&w2h, g_w2h);
    cudaGetSymbolAddress((void**)&w2l, g_w2l);

    cudaFuncSetAttribute(gemm_bf16split<true>,  cudaFuncAttributeMaxDynamicSharedMemorySize, GEMM_SMEM);
    cudaFuncSetAttribute(gemm_bf16split<false>, cudaFuncAttributeMaxDynamicSharedMemorySize, GEMM_SMEM);

    // 0) bf16 hi/lo splits of x and w_qkv
    cvt_split<<<(int)(((long)B_*CDIM*NTOK/4 + 255)/256), 256>>>(x, xh, xl, (long)B_*CDIM*NTOK);
    cvt_split<<<(O1*CDIM/4 + 255)/256, 256>>>(w_qkv, wh, wl, (long)O1*CDIM);

    // 1) qkv = w_qkv @ x with fused epilogues (m-fastest grid for L2 reuse of x)
    gemm_bf16split<true><<<dim3(O1/BM, NTOK/BN, B_), 256, GEMM_SMEM>>>(
        wh, wl, xh, xl, qkv, CDIM, NTOK,
        0L, (long)CDIM*NTOK, (long)O1*NTOK);

    // 2) finish k row sums
    ksum_reduce_kernel<<<B_ * 256, 256>>>();

    // 3) partial contexts
    ctx_part_kernel<<<dim3(64, HEADS, B_), 128>>>();

    // 4) reduce + normalize contexts
    ctx_reduce_kernel<<<(B_ * HEADS * DH * DH) / 256, 256>>>();

    // 5) fold output weight with context -> bf16 hi/lo
    fold_w2_kernel<<<(B_ * 256 * 256) / 256, 256>>>(w_out);

    // 6) out = W2 @ q  (plain epilogue; m-fastest grid for L2 reuse of q)
    gemm_bf16split<false><<<dim3(CDIM/BM, NTOK/BN, B_), 256, GEMM_SMEM>>>(
        w2h, w2l, qh, ql, out, CDIM, NTOK,
        (long)CDIM*CDIM, (long)CDIM*NTOK, (long)CDIM*NTOK);
}

// round 10
// speedup vs baseline: 1.0175x; 1.0175x over previous
#include <cuda_runtime.h>
#include <cuda_bf16.h>
#include <cstdint>
#include <cstddef>
#include <math.h>

// Problem constants
#define B_    2
#define CDIM  256
#define NTOK  32768          // 32*32*32 tokens
#define HEADS 8
#define DH    32
#define O1    768            // 3 * HEADS * DH

// GEMM tiling
#define BM 128
#define BN 128
#define BK 32
#define APITCH 40            // 32 + 8 bf16 pad  (80B rows -> conflict-free ldmatrix)
#define BPITCH 136           // 128 + 8 bf16 pad (272B rows -> conflict-free ldmatrix.trans)
#define OA_H 0
#define OA_L (BM*APITCH)                 // 5120
#define OB_H (2*BM*APITCH)               // 10240
#define OB_L (2*BM*APITCH + BK*BPITCH)   // 14592
#define BUFE (2*BM*APITCH + 2*BK*BPITCH) // 18944 bf16 elems per stage
#define GEMM_SMEM (2*BUFE*2)             // bytes (double buffered) = 75776
#define EPI_PITCH 129                    // fp32 epilogue scratch pitch

// ---------------------------------------------------------------------------
// Scratch (device globals; no cudaMalloc allowed)
// ---------------------------------------------------------------------------
__device__ float g_qkv[(size_t)B_ * O1 * NTOK];                 // q(unused) | exp(k) | v, fp32
__device__ float g_ksum[B_ * 256];
__device__ float g_ksum_part[B_ * 256 * 256];                    // [b][krow][ntile]
__device__ float g_ctx_part[(size_t)B_ * HEADS * 256 * DH * DH];
__device__ float g_ctx[B_ * HEADS * DH * DH];
__device__ __align__(16) __nv_bfloat16 g_xh[(size_t)B_*CDIM*NTOK];
__device__ __align__(16) __nv_bfloat16 g_xl[(size_t)B_*CDIM*NTOK];
__device__ __align__(16) __nv_bfloat16 g_qh[(size_t)B_*CDIM*NTOK];
__device__ __align__(16) __nv_bfloat16 g_ql[(size_t)B_*CDIM*NTOK];
__device__ __align__(16) __nv_bfloat16 g_wh[O1*CDIM];
__device__ __align__(16) __nv_bfloat16 g_wl[O1*CDIM];
__device__ __align__(16) __nv_bfloat16 g_w2h[B_*CDIM*CDIM];
__device__ __align__(16) __nv_bfloat16 g_w2l[B_*CDIM*CDIM];

// ---------------------------------------------------------------------------
// PTX helpers
// ---------------------------------------------------------------------------
#define CP16(dst, src) \
    asm volatile("cp.async.cg.shared.global [%0], [%1], 16;" :: "r"(dst), "l"(src) : "memory")
#define CP_COMMIT() asm volatile("cp.async.commit_group;" ::: "memory")
#define CP_WAIT0()  asm volatile("cp.async.wait_group 0;"  ::: "memory")

#define LDSM4(r0,r1,r2,r3,a) \
    asm volatile("ldmatrix.sync.aligned.m8n8.x4.shared.b16 {%0,%1,%2,%3}, [%4];" \
                 : "=r"(r0),"=r"(r1),"=r"(r2),"=r"(r3) : "r"(a))
#define LDSM4T(r0,r1,r2,r3,a) \
    asm volatile("ldmatrix.sync.aligned.m8n8.x4.trans.shared.b16 {%0,%1,%2,%3}, [%4];" \
                 : "=r"(r0),"=r"(r1),"=r"(r2),"=r"(r3) : "r"(a))

#define MMA1(d, a, b) \
    asm volatile("mma.sync.aligned.m16n8k16.row.col.f32.bf16.bf16.f32 " \
                 "{%0,%1,%2,%3},{%4,%5,%6,%7},{%8,%9},{%0,%1,%2,%3};" \
                 : "+f"((d)[0]),"+f"((d)[1]),"+f"((d)[2]),"+f"((d)[3]) \
                 : "r"((a)[0]),"r"((a)[1]),"r"((a)[2]),"r"((a)[3]), \
                   "r"((b)[0]),"r"((b)[1]))

// ---------------------------------------------------------------------------
// Split-bf16 tensor-core GEMM with optional fused qkv epilogue.
// C[M,N] = A[M,K] * B[K,N]; A,B as (hi,lo) bf16 pairs, 3-term split
// (ah*bh + ah*bl + al*bh), issued as three nt-sweeps so same-accumulator
// MMAs sit 4 apart (covers HMMA RAW latency; MMA3-adjacent issue was the
// R5/R7 tensor-pipe stall).
// 128x128x32 tiles, 8 warps (2x4), warp tile 64x32, m16n8k16 MMAs.
// Grid: (N/128, M/128, batch).
// FUSE_QKV: blockIdx.y 0-1 -> q softmax -> g_qh/g_ql bf16;
//           blockIdx.y 2-3 -> exp(k) -> C fp32 + partial row sums;
//           blockIdx.y 4-5 -> plain fp32 store (v).
// ---------------------------------------------------------------------------
template <bool FUSE_QKV>
__global__ __launch_bounds__(256, 2)
void gemm_bf16split(const __nv_bfloat16* __restrict__ Ah, const __nv_bfloat16* __restrict__ Al,
                    const __nv_bfloat16* __restrict__ Bh, const __nv_bfloat16* __restrict__ Bl,
                    float* __restrict__ C, int K, int N,
                    long sA, long sB, long sC)
{
    extern __shared__ __nv_bfloat16 smbuf[];
    const int bz = blockIdx.z;
    Ah += bz * sA;  Al += bz * sA;
    Bh += bz * sB;  Bl += bz * sB;
    C  += bz * sC;

    const int tid   = threadIdx.x;
    const int lane  = tid & 31;
    const int wid   = tid >> 5;
    const int warp_m = wid >> 2;       // 0..1 -> 64-row slab
    const int warp_n = wid & 3;        // 0..3 -> 32-col slab
    const int bn = blockIdx.x * BN;
    const int bm = blockIdx.y * BM;

    const uint32_t su = (uint32_t)__cvta_generic_to_shared(smbuf);

    const int rowA = (lane & 7) + ((lane >> 3) & 1) * 8;
    const int colA = (lane >> 4) * 8;
    const uint32_t aOff = (uint32_t)(((warp_m * 64 + rowA) * APITCH + colA) * 2);
    const int rowB = (lane & 7) + ((lane >> 3) & 1) * 8;
    const int colB = warp_n * 32 + ((lane >> 4) & 1) * 8;
    const uint32_t bOff = (uint32_t)((rowB * BPITCH + colB) * 2);

    float acc[4][4][4];
#pragma unroll
    for (int i = 0; i < 4; i++)
#pragma unroll
        for (int j = 0; j < 4; j++)
#pragma unroll
            for (int r = 0; r < 4; r++) acc[i][j][r] = 0.f;

#define LOAD_HALF(buf, kt, id) do {                                                  \
    int ra = (id) >> 2, ca = ((id) & 3) * 8;                                         \
    uint32_t dA = su + (uint32_t)(((buf)*BUFE + ra*APITCH + ca) * 2);                \
    CP16(dA + OA_H*2, Ah + (long)(bm + ra) * K + (kt) + ca);                         \
    CP16(dA + OA_L*2, Al + (long)(bm + ra) * K + (kt) + ca);                         \
    int rb = (id) >> 4, cb = ((id) & 15) * 8;                                        \
    uint32_t dB = su + (uint32_t)(((buf)*BUFE + rb*BPITCH + cb) * 2);                \
    CP16(dB + OB_H*2, Bh + (long)((kt) + rb) * N + bn + cb);                         \
    CP16(dB + OB_L*2, Bl + (long)((kt) + rb) * N + bn + cb);                         \
} while (0)

#define LOAD_TILE(buf, kt) do {                                                      \
    LOAD_HALF(buf, kt, tid);                                                         \
    LOAD_HALF(buf, kt, tid + 256);                                                   \
    CP_COMMIT();                                                                     \
} while (0)

    LOAD_TILE(0, 0);
    CP_WAIT0();
    __syncthreads();

    int buf = 0;
    for (int kt = BK; kt <= K; kt += BK) {
        if (kt < K) LOAD_TILE(buf ^ 1, kt);

        const uint32_t stage = su + (uint32_t)(buf * BUFE * 2);
#pragma unroll
        for (int kk = 0; kk < BK; kk += 16) {
            uint32_t fbh[4][2], fbl[4][2];
#pragma unroll
            for (int pr = 0; pr < 2; pr++) {
                uint32_t adH = stage + (uint32_t)(OB_H*2) + (uint32_t)(kk*BPITCH*2) + bOff + (uint32_t)(pr*32);
                LDSM4T(fbh[2*pr][0], fbh[2*pr][1], fbh[2*pr+1][0], fbh[2*pr+1][1], adH);
                uint32_t adL = stage + (uint32_t)(OB_L*2) + (uint32_t)(kk*BPITCH*2) + bOff + (uint32_t)(pr*32);
                LDSM4T(fbl[2*pr][0], fbl[2*pr][1], fbl[2*pr+1][0], fbl[2*pr+1][1], adL);
            }
#pragma unroll
            for (int mt = 0; mt < 4; mt++) {
                uint32_t fah[4], fal[4];
                uint32_t aaH = stage + (uint32_t)(OA_H*2) + aOff + (uint32_t)((mt*16*APITCH + kk) * 2);
                LDSM4(fah[0], fah[1], fah[2], fah[3], aaH);
                uint32_t aaL = stage + (uint32_t)(OA_L*2) + aOff + (uint32_t)((mt*16*APITCH + kk) * 2);
                LDSM4(fal[0], fal[1], fal[2], fal[3], aaL);
                // Three nt-sweeps: same-acc MMAs 4 apart (RAW latency hidden);
                // per-acc term order hh -> hl -> lh preserved (bitwise identical).
#pragma unroll
                for (int nt = 0; nt < 4; nt++) MMA1(acc[mt][nt], fah, fbh[nt]);
#pragma unroll
                for (int nt = 0; nt < 4; nt++) MMA1(acc[mt][nt], fah, fbl[nt]);
#pragma unroll
                for (int nt = 0; nt < 4; nt++) MMA1(acc[mt][nt], fal, fbh[nt]);
            }
        }

        if (kt < K) {
            CP_WAIT0();
            __syncthreads();
            buf ^= 1;
        }
    }
#undef LOAD_TILE
#undef LOAD_HALF

    const int r0 = warp_m * 64 + (lane >> 2);
    const int c0 = warp_n * 32 + (lane & 3) * 2;

    if (FUSE_QKV && blockIdx.y < 2) {
        // ---- q path: softmax over d (32 rows per head), write bf16 hi/lo ----
        __syncthreads();                      // main-loop smem reads done
        float* sf = (float*)smbuf;
#pragma unroll
        for (int mt = 0; mt < 4; mt++)
#pragma unroll
            for (int nt = 0; nt < 4; nt++) {
                int r = r0 + mt * 16, c = c0 + nt * 8;
                sf[r * EPI_PITCH + c]           = acc[mt][nt][0];
                sf[r * EPI_PITCH + c + 1]       = acc[mt][nt][1];
                sf[(r + 8) * EPI_PITCH + c]     = acc[mt][nt][2];
                sf[(r + 8) * EPI_PITCH + c + 1] = acc[mt][nt][3];
            }
        __syncthreads();

        const int col = tid & 127;
        const int h0  = tid >> 7;            // 0 or 1
        const long n  = bn + col;
#pragma unroll
        for (int hh = h0; hh < 4; hh += 2) {
            float v[DH];
            float mx = -1e30f;
#pragma unroll
            for (int d = 0; d < DH; d++) {
                v[d] = sf[(hh * DH + d) * EPI_PITCH + col];
                mx = fmaxf(mx, v[d]);
            }
            float s = 0.f;
#pragma unroll
            for (int d = 0; d < DH; d++) { v[d] = expf(v[d] - mx); s += v[d]; }
            float inv = 1.f / s;
            const int hglob = blockIdx.y * 4 + hh;
            __nv_bfloat16* qh = g_qh + ((long)bz * CDIM + hglob * DH) * NTOK + n;
            __nv_bfloat16* ql = g_ql + ((long)bz * CDIM + hglob * DH) * NTOK + n;
#pragma unroll
            for (int d = 0; d < DH; d++) {
                float q = v[d] * inv;
                __nv_bfloat16 hb = __float2bfloat16(q);
                qh[(long)d * NTOK] = hb;
                ql[(long)d * NTOK] = __float2bfloat16(q - __bfloat162float(hb));
            }
        }
    } else if (FUSE_QKV && blockIdx.y < 4) {
        // ---- k path: exp in regs -> gmem fp32 + smem; then partial row sums ----
        __syncthreads();
        float* sf = (float*)smbuf;
#pragma unroll
        for (int mt = 0; mt < 4; mt++)
#pragma unroll
            for (int nt = 0; nt < 4; nt++) {
                int r = r0 + mt * 16, c = c0 + nt * 8;
                float e0 = expf(acc[mt][nt][0]);
                float e1 = expf(acc[mt][nt][1]);
                float e2 = expf(acc[mt][nt][2]);
                float e3 = expf(acc[mt][nt][3]);
                float* cp = C + (long)(bm + r) * N + bn + c;
                *(float2*)cp               = make_float2(e0, e1);
                *(float2*)(cp + 8*(long)N) = make_float2(e2, e3);
                sf[r * EPI_PITCH + c]           = e0;
                sf[r * EPI_PITCH + c + 1]       = e1;
                sf[(r + 8) * EPI_PITCH + c]     = e2;
                sf[(r + 8) * EPI_PITCH + c + 1] = e3;
            }
        __syncthreads();
        if (tid < 128) {
            float s = 0.f;
#pragma unroll 8
            for (int c = 0; c < 128; c++) s += sf[tid * EPI_PITCH + c];
            int kr = (blockIdx.y - 2) * 128 + tid;   // 0..255
            g_ksum_part[((long)bz * 256 + kr) * 256 + blockIdx.x] = s;
        }
    } else {
        // ---- plain fp32 store (v tiles, and all of GEMM3) ----
#pragma unroll
        for (int mt = 0; mt < 4; mt++)
#pragma unroll
            for (int nt = 0; nt < 4; nt++) {
                long row = bm + r0 + mt * 16;
                float* cp = C + row * (long)N + bn + c0 + nt * 8;
                *(float2*)cp               = make_float2(acc[mt][nt][0], acc[mt][nt][1]);
                *(float2*)(cp + 8*(long)N) = make_float2(acc[mt][nt][2], acc[mt][nt][3]);
            }
    }
}

// ---------------------------------------------------------------------------
// fp32 -> (bf16 hi, bf16 lo) split conversion, 4 elems/thread.
// ---------------------------------------------------------------------------
__global__ void cvt_split(const float* __restrict__ src,
                          __nv_bfloat16* __restrict__ h, __nv_bfloat16* __restrict__ l,
                          long n)
{
    long i = ((long)blockIdx.x * blockDim.x + threadIdx.x) * 4;
    if (i >= n) return;
    float4 v = *(const float4*)(src + i);
    float a[4] = {v.x, v.y, v.z, v.w};
#pragma unroll
    for (int j = 0; j < 4; j++) {
        __nv_bfloat16 hh = __float2bfloat16(a[j]);
        h[i + j] = hh;
        l[i + j] = __float2bfloat16(a[j] - __bfloat162float(hh));
    }
}

// ---------------------------------------------------------------------------
// Reduce per-ntile partial k row sums: 256 -> 1 per (b, krow). Deterministic.
// ---------------------------------------------------------------------------
__global__ void ksum_reduce_kernel()
{
    int b  = blockIdx.x >> 8;
    int kr = blockIdx.x & 255;
    __shared__ float red[256];
    red[threadIdx.x] = g_ksum_part[((long)b * 256 + kr) * 256 + threadIdx.x];
    __syncthreads();
    for (int o = 128; o > 0; o >>= 1) {
        if (threadIdx.x < o) red[threadIdx.x] += red[threadIdx.x + o];
        __syncthreads();
    }
    if (threadIdx.x == 0) g_ksum[b * 256 + kr] = red[0];
}

// ---------------------------------------------------------------------------
// Partial contexts over 128-token stripes.
// ---------------------------------------------------------------------------
__global__ __launch_bounds__(128)
void ctx_part_kernel()
{
    const int chunk = blockIdx.x;        // 0..63 (512 tokens each)
    const int h     = blockIdx.y;
    const int b     = blockIdx.z;
    const int w     = threadIdx.x / 32;  // stripe within chunk (128 tokens)
    const int lane  = threadIdx.x % 32;

    __shared__ float ek_s[4][32][33];
    __shared__ float v_s [4][32][33];

    const long kbase = ((long)b * O1 + 256 + h * DH) * NTOK;
    const long vbase = ((long)b * O1 + 512 + h * DH) * NTOK;
    const int  n_base = chunk * 512 + w * 128;

    const int ti = lane / 4;
    const int tj = lane % 4;

    float acc[4][8];
#pragma unroll
    for (int i = 0; i < 4; i++)
#pragma unroll
        for (int j = 0; j < 8; j++) acc[i][j] = 0.f;

    for (int n0 = 0; n0 < 128; n0 += 32) {
#pragma unroll
        for (int p = 0; p < 8; p++) {
            int fl = p * 32 + lane;
            int d = fl / 8, nq = fl % 8;
            float4 ke = *(const float4*)(g_qkv + kbase + (long)d * NTOK + n_base + n0 + nq * 4);
            ek_s[w][nq * 4 + 0][d] = ke.x;
            ek_s[w][nq * 4 + 1][d] = ke.y;
            ek_s[w][nq * 4 + 2][d] = ke.z;
            ek_s[w][nq * 4 + 3][d] = ke.w;
            float4 ve = *(const float4*)(g_qkv + vbase + (long)d * NTOK + n_base + n0 + nq * 4);
            v_s[w][nq * 4 + 0][d] = ve.x;
            v_s[w][nq * 4 + 1][d] = ve.y;
            v_s[w][nq * 4 + 2][d] = ve.z;
            v_s[w][nq * 4 + 3][d] = ve.w;
        }
        __syncwarp();
#pragma unroll 8
        for (int n = 0; n < 32; n++) {
            float a[4], bb[8];
#pragma unroll
            for (int i = 0; i < 4; i++) a[i] = ek_s[w][n][ti * 4 + i];
#pragma unroll
            for (int j = 0; j < 8; j++) bb[j] = v_s[w][n][tj * 8 + j];
#pragma unroll
            for (int i = 0; i < 4; i++)
#pragma unroll
                for (int j = 0; j < 8; j++)
                    acc[i][j] = fmaf(a[i], bb[j], acc[i][j]);
        }
        __syncwarp();
    }

    const int stripe = chunk * 4 + w;    // 0..255
    float* out = g_ctx_part + ((long)(b * HEADS + h) * 256 + stripe) * (DH * DH);
#pragma unroll
    for (int i = 0; i < 4; i++)
#pragma unroll
        for (int j = 0; j < 8; j++)
            out[(ti * 4 + i) * DH + tj * 8 + j] = acc[i][j];
}

__global__ void ctx_reduce_kernel()
{
    int idx = blockIdx.x * blockDim.x + threadIdx.x;  // < B_*HEADS*1024
    int de = idx % (DH * DH);
    int bh = idx / (DH * DH);
    int d  = de / DH;
    int b  = bh / HEADS, h = bh % HEADS;
    const float* p = g_ctx_part + (long)bh * 256 * (DH * DH) + de;
    float s = 0.f;
#pragma unroll 8
    for (int st = 0; st < 256; st++) s += p[(long)st * (DH * DH)];
    float inv = 1.f / g_ksum[b * 256 + h * DH + d];
    g_ctx[(long)bh * (DH * DH) + de] = s * inv;
}

// ---------------------------------------------------------------------------
// Fold w_out with context; emit bf16 hi/lo W2.
// ---------------------------------------------------------------------------
__global__ void fold_w2_kernel(const float* __restrict__ w_out)
{
    int idx = blockIdx.x * blockDim.x + threadIdx.x;  // < B_*256*256
    int hd = idx % 256;
    int o  = (idx / 256) % 256;
    int b  = idx / 65536;
    int h = hd / DH, d = hd % DH;
    const float* wrow = w_out + o * 256 + h * DH;
    const float* ctx  = g_ctx + ((long)(b * HEADS + h) * DH + d) * DH;
    float s = 0.f;
#pragma unroll
    for (int e = 0; e < DH; e++) s = fmaf(wrow[e], ctx[e], s);
    __nv_bfloat16 hh = __float2bfloat16(s);
    g_w2h[(long)b * 65536 + o * 256 + hd] = hh;
    g_w2l[(long)b * 65536 + o * 256 + hd] = __float2bfloat16(s - __bfloat162float(hh));
}

// ---------------------------------------------------------------------------
// Launch
// ---------------------------------------------------------------------------
extern "C" void kernel_launch(void* const* d_in, const int* in_sizes, int n_in,
                              void* d_out, int out_size)
{
    const float* x     = (const float*)d_in[0];  // [2,256,32768]
    const float* w_qkv = (const float*)d_in[1];  // [768,256]
    const float* w_out = (const float*)d_in[2];  // [256,256]
    float* out = (float*)d_out;                  // [2,256,32768]

    float *qkv = nullptr;
    __nv_bfloat16 *xh, *xl, *qh, *ql, *wh, *wl, *w2h, *w2l;
    cudaGetSymbolAddress((void**)&qkv, g_qkv);
    cudaGetSymbolAddress((void**)&xh,  g_xh);
    cudaGetSymbolAddress((void**)&xl,  g_xl);
    cudaGetSymbolAddress((void**)&qh,  g_qh);
    cudaGetSymbolAddress((void**)&ql,  g_ql);
    cudaGetSymbolAddress((void**)&wh,  g_wh);
    cudaGetSymbolAddress((void**)&wl,  g_wl);
    cudaGetSymbolAddress((void**)&w2h, g_w2h);
    cudaGetSymbolAddress((void**)&w2l, g_w2l);

    cudaFuncSetAttribute(gemm_bf16split<true>,  cudaFuncAttributeMaxDynamicSharedMemorySize, GEMM_SMEM);
    cudaFuncSetAttribute(gemm_bf16split<false>, cudaFuncAttributeMaxDynamicSharedMemorySize, GEMM_SMEM);

    // 0) bf16 hi/lo splits of x and w_qkv
    cvt_split<<<(int)(((long)B_*CDIM*NTOK/4 + 255)/256), 256>>>(x, xh, xl, (long)B_*CDIM*NTOK);
    cvt_split<<<(O1*CDIM/4 + 255)/256, 256>>>(w_qkv, wh, wl, (long)O1*CDIM);

    // 1) qkv = w_qkv @ x with fused epilogues (R7 grid: n fastest-varying)
    gemm_bf16split<true><<<dim3(NTOK/BN, O1/BM, B_), 256, GEMM_SMEM>>>(
        wh, wl, xh, xl, qkv, CDIM, NTOK,
        0L, (long)CDIM*NTOK, (long)O1*NTOK);

    // 2) finish k row sums
    ksum_reduce_kernel<<<B_ * 256, 256>>>();

    // 3) partial contexts
    ctx_part_kernel<<<dim3(64, HEADS, B_), 128>>>();

    // 4) reduce + normalize contexts
    ctx_reduce_kernel<<<(B_ * HEADS * DH * DH) / 256, 256>>>();

    // 5) fold output weight with context -> bf16 hi/lo
    fold_w2_kernel<<<(B_ * 256 * 256) / 256, 256>>>(w_out);

    // 6) out = W2 @ q  (plain epilogue)
    gemm_bf16split<false><<<dim3(NTOK/BN, CDIM/BM, B_), 256, GEMM_SMEM>>>(
        w2h, w2l, qh, ql, out, CDIM, NTOK,
        (long)CDIM*CDIM, (long)CDIM*NTOK, (long)CDIM*NTOK);
}

// round 11
// speedup vs baseline: 1.0952x; 1.0764x over previous
#include <cuda_runtime.h>
#include <cuda_bf16.h>
#include <cstdint>
#include <cstddef>
#include <math.h>

// Problem constants
#define B_    2
#define CDIM  256
#define NTOK  32768          // 32*32*32 tokens
#define HEADS 8
#define DH    32
#define O1    768            // 3 * HEADS * DH

// GEMM tiling
#define BM 128
#define BN 128
#define BK 32
#define APITCH 40            // 32 + 8 bf16 pad  (80B rows -> conflict-free ldmatrix)
#define BPITCH 136           // 128 + 8 bf16 pad (272B rows -> conflict-free ldmatrix.trans)
#define OA_H 0
#define OA_L (BM*APITCH)                 // 5120
#define OB_H (2*BM*APITCH)               // 10240
#define OB_L (2*BM*APITCH + BK*BPITCH)   // 14592
#define BUFE (2*BM*APITCH + 2*BK*BPITCH) // 18944 bf16 elems per stage
#define GEMM_SMEM (2*BUFE*2)             // bytes (double buffered) = 75776
#define EPI_PITCH 129                    // fp32 epilogue scratch pitch

// ---------------------------------------------------------------------------
// Scratch (device globals; no cudaMalloc allowed)
// ---------------------------------------------------------------------------
__device__ float g_qkv[(size_t)B_ * O1 * NTOK];                 // q(unused) | exp(k) | v, fp32
__device__ float g_ksum[B_ * 256];
__device__ float g_ksum_part[B_ * 256 * 256];                    // [b][krow][ntile]
__device__ float g_ctx_part[(size_t)B_ * HEADS * 256 * DH * DH];
__device__ float g_ctx[B_ * HEADS * DH * DH];
__device__ __align__(16) __nv_bfloat16 g_qh[(size_t)B_*CDIM*NTOK];
__device__ __align__(16) __nv_bfloat16 g_ql[(size_t)B_*CDIM*NTOK];
__device__ __align__(16) __nv_bfloat16 g_wh[O1*CDIM];
__device__ __align__(16) __nv_bfloat16 g_wl[O1*CDIM];
__device__ __align__(16) __nv_bfloat16 g_w2h[B_*CDIM*CDIM];
__device__ __align__(16) __nv_bfloat16 g_w2l[B_*CDIM*CDIM];

// ---------------------------------------------------------------------------
// PTX helpers
// ---------------------------------------------------------------------------
#define CP16(dst, src) \
    asm volatile("cp.async.cg.shared.global [%0], [%1], 16;" :: "r"(dst), "l"(src) : "memory")
#define CP_COMMIT() asm volatile("cp.async.commit_group;" ::: "memory")
#define CP_WAIT0()  asm volatile("cp.async.wait_group 0;"  ::: "memory")

#define LDSM4(r0,r1,r2,r3,a) \
    asm volatile("ldmatrix.sync.aligned.m8n8.x4.shared.b16 {%0,%1,%2,%3}, [%4];" \
                 : "=r"(r0),"=r"(r1),"=r"(r2),"=r"(r3) : "r"(a))
#define LDSM4T(r0,r1,r2,r3,a) \
    asm volatile("ldmatrix.sync.aligned.m8n8.x4.trans.shared.b16 {%0,%1,%2,%3}, [%4];" \
                 : "=r"(r0),"=r"(r1),"=r"(r2),"=r"(r3) : "r"(a))

#define MMA3(d, a, b) \
    asm volatile("mma.sync.aligned.m16n8k16.row.col.f32.bf16.bf16.f32 " \
                 "{%0,%1,%2,%3},{%4,%5,%6,%7},{%8,%9},{%0,%1,%2,%3};" \
                 : "+f"((d)[0]),"+f"((d)[1]),"+f"((d)[2]),"+f"((d)[3]) \
                 : "r"((a)[0]),"r"((a)[1]),"r"((a)[2]),"r"((a)[3]), \
                   "r"((b)[0]),"r"((b)[1]))

// ---------------------------------------------------------------------------
// Split-bf16 tensor-core GEMM. C[M,N] = A[M,K] * B[K,N]; 3-term split
// (ah*bh + ah*bl + al*bh), 128x128x32 tiles, 8 warps, m16n8k16 MMAs.
// MODE 1 (GEMM1): B is fp32 (x) — loaded via registers, converted to bf16
//   hi/lo in-kernel (deletes the standalone cvt pass; byte count identical).
//   Fused epilogues: blockIdx.y 0-1 q-softmax->bf16, 2-3 exp(k)+row sums,
//   4-5 plain fp32 (v).
// MODE 0 (GEMM3): B is pre-split bf16 hi/lo (q); plain fp32 epilogue.
// ---------------------------------------------------------------------------
template <int MODE>
__global__ __launch_bounds__(256, 2)
void gemm_bf16split(const __nv_bfloat16* __restrict__ Ah, const __nv_bfloat16* __restrict__ Al,
                    const __nv_bfloat16* __restrict__ Bh, const __nv_bfloat16* __restrict__ Bl,
                    const float* __restrict__ Bf,
                    float* __restrict__ C, int K, int N,
                    long sA, long sB, long sC)
{
    extern __shared__ __nv_bfloat16 smbuf[];
    const int bz = blockIdx.z;
    Ah += bz * sA;  Al += bz * sA;
    if (MODE == 0) { Bh += bz * sB;  Bl += bz * sB; }
    else           { Bf += bz * sB; }
    C  += bz * sC;

    const int tid   = threadIdx.x;
    const int lane  = tid & 31;
    const int wid   = tid >> 5;
    const int warp_m = wid >> 2;       // 0..1 -> 64-row slab
    const int warp_n = wid & 3;        // 0..3 -> 32-col slab
    const int bn = blockIdx.x * BN;
    const int bm = blockIdx.y * BM;

    const uint32_t su = (uint32_t)__cvta_generic_to_shared(smbuf);

    const int rowA = (lane & 7) + ((lane >> 3) & 1) * 8;
    const int colA = (lane >> 4) * 8;
    const uint32_t aOff = (uint32_t)(((warp_m * 64 + rowA) * APITCH + colA) * 2);
    const int rowB = (lane & 7) + ((lane >> 3) & 1) * 8;
    const int colB = warp_n * 32 + ((lane >> 4) & 1) * 8;
    const uint32_t bOff = (uint32_t)((rowB * BPITCH + colB) * 2);

    float acc[4][4][4];
#pragma unroll
    for (int i = 0; i < 4; i++)
#pragma unroll
        for (int j = 0; j < 4; j++)
#pragma unroll
            for (int r = 0; r < 4; r++) acc[i][j][r] = 0.f;

    // fp32 B staging registers (MODE 1): 4 float4 = rows tid/8 pattern below
    float4 breg[4];

    // --- A tile: cp.async, both modes (512 x 16B per plane) ---
#define LOAD_A(buf, kt) do {                                                         \
    _Pragma("unroll")                                                                \
    for (int p = 0; p < 2; p++) {                                                    \
        int id = tid + p * 256;                                                      \
        int ra = id >> 2, ca = (id & 3) * 8;                                         \
        uint32_t dA = su + (uint32_t)(((buf)*BUFE + ra*APITCH + ca) * 2);            \
        CP16(dA + OA_H*2, Ah + (long)(bm + ra) * K + (kt) + ca);                     \
        CP16(dA + OA_L*2, Al + (long)(bm + ra) * K + (kt) + ca);                     \
    }                                                                                \
} while (0)

    // --- B tile MODE 0: cp.async bf16 hi/lo ---
#define LOAD_B0(buf, kt) do {                                                        \
    _Pragma("unroll")                                                                \
    for (int p = 0; p < 2; p++) {                                                    \
        int id = tid + p * 256;                                                      \
        int rb = id >> 4, cb = (id & 15) * 8;                                        \
        uint32_t dB = su + (uint32_t)(((buf)*BUFE + rb*BPITCH + cb) * 2);            \
        CP16(dB + OB_H*2, Bh + (long)((kt) + rb) * N + bn + cb);                     \
        CP16(dB + OB_L*2, Bl + (long)((kt) + rb) * N + bn + cb);                     \
    }                                                                                \
} while (0)

    // --- B tile MODE 1: LDG fp32 into breg (issue early; latency hides under MMAs)
#define LDG_B(kt) do {                                                               \
    _Pragma("unroll")                                                                \
    for (int p = 0; p < 4; p++) {                                                    \
        int id = tid + p * 256;                                                      \
        int rb = id >> 5, cb = (id & 31) * 4;                                        \
        breg[p] = *(const float4*)(Bf + (long)((kt) + rb) * N + bn + cb);            \
    }                                                                                \
} while (0)

    // --- convert breg -> bf16 hi/lo smem planes (identical math to cvt_split) ---
#define CVT_STS_B(buf) do {                                                          \
    _Pragma("unroll")                                                                \
    for (int p = 0; p < 4; p++) {                                                    \
        int id = tid + p * 256;                                                      \
        int rb = id >> 5, cb = (id & 31) * 4;                                        \
        float vv[4] = {breg[p].x, breg[p].y, breg[p].z, breg[p].w};                  \
        __nv_bfloat16 hb4[4], lb4[4];                                                \
        _Pragma("unroll")                                                            \
        for (int j = 0; j < 4; j++) {                                                \
            hb4[j] = __float2bfloat16(vv[j]);                                        \
            lb4[j] = __float2bfloat16(vv[j] - __bfloat162float(hb4[j]));             \
        }                                                                            \
        __nv_bfloat16* bp = smbuf + (buf)*BUFE + rb*BPITCH + cb;                     \
        *(uint2*)(bp + OB_H) = *(uint2*)hb4;                                         \
        *(uint2*)(bp + OB_L) = *(uint2*)lb4;                                         \
    }                                                                                \
} while (0)

    // Prologue
    LOAD_A(0, 0);
    if (MODE == 0) LOAD_B0(0, 0);
    CP_COMMIT();
    if (MODE == 1) LDG_B(0);
    CP_WAIT0();
    if (MODE == 1) CVT_STS_B(0);
    __syncthreads();

    int buf = 0;
    for (int kt = BK; kt <= K; kt += BK) {
        if (kt < K) {
            LOAD_A(buf ^ 1, kt);
            if (MODE == 0) LOAD_B0(buf ^ 1, kt);
            CP_COMMIT();
            if (MODE == 1) LDG_B(kt);
        }

        const uint32_t stage = su + (uint32_t)(buf * BUFE * 2);
#pragma unroll
        for (int kk = 0; kk < BK; kk += 16) {
            uint32_t fbh[4][2], fbl[4][2];
#pragma unroll
            for (int pr = 0; pr < 2; pr++) {
                uint32_t adH = stage + (uint32_t)(OB_H*2) + (uint32_t)(kk*BPITCH*2) + bOff + (uint32_t)(pr*32);
                LDSM4T(fbh[2*pr][0], fbh[2*pr][1], fbh[2*pr+1][0], fbh[2*pr+1][1], adH);
                uint32_t adL = stage + (uint32_t)(OB_L*2) + (uint32_t)(kk*BPITCH*2) + bOff + (uint32_t)(pr*32);
                LDSM4T(fbl[2*pr][0], fbl[2*pr][1], fbl[2*pr+1][0], fbl[2*pr+1][1], adL);
            }
#pragma unroll
            for (int mt = 0; mt < 4; mt++) {
                uint32_t fah[4], fal[4];
                uint32_t aaH = stage + (uint32_t)(OA_H*2) + aOff + (uint32_t)((mt*16*APITCH + kk) * 2);
                LDSM4(fah[0], fah[1], fah[2], fah[3], aaH);
                uint32_t aaL = stage + (uint32_t)(OA_L*2) + aOff + (uint32_t)((mt*16*APITCH + kk) * 2);
                LDSM4(fal[0], fal[1], fal[2], fal[3], aaL);
#pragma unroll
                for (int nt = 0; nt < 4; nt++) {
                    MMA3(acc[mt][nt], fah, fbh[nt]);
                    MMA3(acc[mt][nt], fah, fbl[nt]);
                    MMA3(acc[mt][nt], fal, fbh[nt]);
                }
            }
        }

        if (kt < K) {
            CP_WAIT0();
            if (MODE == 1) CVT_STS_B(buf ^ 1);
            __syncthreads();
            buf ^= 1;
        }
    }
#undef LOAD_A
#undef LOAD_B0
#undef LDG_B
#undef CVT_STS_B

    const int r0 = warp_m * 64 + (lane >> 2);
    const int c0 = warp_n * 32 + (lane & 3) * 2;

    if (MODE == 1 && blockIdx.y < 2) {
        // ---- q path: softmax over d (32 rows per head), write bf16 hi/lo ----
        __syncthreads();                      // main-loop smem reads done
        float* sf = (float*)smbuf;
#pragma unroll
        for (int mt = 0; mt < 4; mt++)
#pragma unroll
            for (int nt = 0; nt < 4; nt++) {
                int r = r0 + mt * 16, c = c0 + nt * 8;
                sf[r * EPI_PITCH + c]           = acc[mt][nt][0];
                sf[r * EPI_PITCH + c + 1]       = acc[mt][nt][1];
                sf[(r + 8) * EPI_PITCH + c]     = acc[mt][nt][2];
                sf[(r + 8) * EPI_PITCH + c + 1] = acc[mt][nt][3];
            }
        __syncthreads();

        const int col = tid & 127;
        const int h0  = tid >> 7;            // 0 or 1
        const long n  = bn + col;
#pragma unroll
        for (int hh = h0; hh < 4; hh += 2) {
            float v[DH];
            float mx = -1e30f;
#pragma unroll
            for (int d = 0; d < DH; d++) {
                v[d] = sf[(hh * DH + d) * EPI_PITCH + col];
                mx = fmaxf(mx, v[d]);
            }
            float s = 0.f;
#pragma unroll
            for (int d = 0; d < DH; d++) { v[d] = expf(v[d] - mx); s += v[d]; }
            float inv = 1.f / s;
            const int hglob = blockIdx.y * 4 + hh;
            __nv_bfloat16* qh = g_qh + ((long)bz * CDIM + hglob * DH) * NTOK + n;
            __nv_bfloat16* ql = g_ql + ((long)bz * CDIM + hglob * DH) * NTOK + n;
#pragma unroll
            for (int d = 0; d < DH; d++) {
                float q = v[d] * inv;
                __nv_bfloat16 hb = __float2bfloat16(q);
                qh[(long)d * NTOK] = hb;
                ql[(long)d * NTOK] = __float2bfloat16(q - __bfloat162float(hb));
            }
        }
    } else if (MODE == 1 && blockIdx.y < 4) {
        // ---- k path: exp in regs -> gmem fp32 + smem; then partial row sums ----
        __syncthreads();
        float* sf = (float*)smbuf;
#pragma unroll
        for (int mt = 0; mt < 4; mt++)
#pragma unroll
            for (int nt = 0; nt < 4; nt++) {
                int r = r0 + mt * 16, c = c0 + nt * 8;
                float e0 = expf(acc[mt][nt][0]);
                float e1 = expf(acc[mt][nt][1]);
                float e2 = expf(acc[mt][nt][2]);
                float e3 = expf(acc[mt][nt][3]);
                float* cp = C + (long)(bm + r) * N + bn + c;
                *(float2*)cp               = make_float2(e0, e1);
                *(float2*)(cp + 8*(long)N) = make_float2(e2, e3);
                sf[r * EPI_PITCH + c]           = e0;
                sf[r * EPI_PITCH + c + 1]       = e1;
                sf[(r + 8) * EPI_PITCH + c]     = e2;
                sf[(r + 8) * EPI_PITCH + c + 1] = e3;
            }
        __syncthreads();
        if (tid < 128) {
            float s = 0.f;
#pragma unroll 8
            for (int c = 0; c < 128; c++) s += sf[tid * EPI_PITCH + c];
            int kr = (blockIdx.y - 2) * 128 + tid;   // 0..255
            g_ksum_part[((long)bz * 256 + kr) * 256 + blockIdx.x] = s;
        }
    } else {
        // ---- plain fp32 store (v tiles, and all of GEMM3) ----
#pragma unroll
        for (int mt = 0; mt < 4; mt++)
#pragma unroll
            for (int nt = 0; nt < 4; nt++) {
                long row = bm + r0 + mt * 16;
                float* cp = C + row * (long)N + bn + c0 + nt * 8;
                *(float2*)cp               = make_float2(acc[mt][nt][0], acc[mt][nt][1]);
                *(float2*)(cp + 8*(long)N) = make_float2(acc[mt][nt][2], acc[mt][nt][3]);
            }
    }
}

// ---------------------------------------------------------------------------
// fp32 -> (bf16 hi, bf16 lo) split conversion (weights only now).
// ---------------------------------------------------------------------------
__global__ void cvt_split(const float* __restrict__ src,
                          __nv_bfloat16* __restrict__ h, __nv_bfloat16* __restrict__ l,
                          long n)
{
    long i = ((long)blockIdx.x * blockDim.x + threadIdx.x) * 4;
    if (i >= n) return;
    float4 v = *(const float4*)(src + i);
    float a[4] = {v.x, v.y, v.z, v.w};
#pragma unroll
    for (int j = 0; j < 4; j++) {
        __nv_bfloat16 hh = __float2bfloat16(a[j]);
        h[i + j] = hh;
        l[i + j] = __float2bfloat16(a[j] - __bfloat162float(hh));
    }
}

// ---------------------------------------------------------------------------
// Reduce per-ntile partial k row sums: 256 -> 1 per (b, krow). Deterministic.
// ---------------------------------------------------------------------------
__global__ void ksum_reduce_kernel()
{
    int b  = blockIdx.x >> 8;
    int kr = blockIdx.x & 255;
    __shared__ float red[256];
    red[threadIdx.x] = g_ksum_part[((long)b * 256 + kr) * 256 + threadIdx.x];
    __syncthreads();
    for (int o = 128; o > 0; o >>= 1) {
        if (threadIdx.x < o) red[threadIdx.x] += red[threadIdx.x + o];
        __syncthreads();
    }
    if (threadIdx.x == 0) g_ksum[b * 256 + kr] = red[0];
}

// ---------------------------------------------------------------------------
// Partial contexts over 128-token stripes.
// ---------------------------------------------------------------------------
__global__ __launch_bounds__(128)
void ctx_part_kernel()
{
    const int chunk = blockIdx.x;        // 0..63 (512 tokens each)
    const int h     = blockIdx.y;
    const int b     = blockIdx.z;
    const int w     = threadIdx.x / 32;  // stripe within chunk (128 tokens)
    const int lane  = threadIdx.x % 32;

    __shared__ float ek_s[4][32][33];
    __shared__ float v_s [4][32][33];

    const long kbase = ((long)b * O1 + 256 + h * DH) * NTOK;
    const long vbase = ((long)b * O1 + 512 + h * DH) * NTOK;
    const int  n_base = chunk * 512 + w * 128;

    const int ti = lane / 4;
    const int tj = lane % 4;

    float acc[4][8];
#pragma unroll
    for (int i = 0; i < 4; i++)
#pragma unroll
        for (int j = 0; j < 8; j++) acc[i][j] = 0.f;

    for (int n0 = 0; n0 < 128; n0 += 32) {
#pragma unroll
        for (int p = 0; p < 8; p++) {
            int fl = p * 32 + lane;
            int d = fl / 8, nq = fl % 8;
            float4 ke = *(const float4*)(g_qkv + kbase + (long)d * NTOK + n_base + n0 + nq * 4);
            ek_s[w][nq * 4 + 0][d] = ke.x;
            ek_s[w][nq * 4 + 1][d] = ke.y;
            ek_s[w][nq * 4 + 2][d] = ke.z;
            ek_s[w][nq * 4 + 3][d] = ke.w;
            float4 ve = *(const float4*)(g_qkv + vbase + (long)d * NTOK + n_base + n0 + nq * 4);
            v_s[w][nq * 4 + 0][d] = ve.x;
            v_s[w][nq * 4 + 1][d] = ve.y;
            v_s[w][nq * 4 + 2][d] = ve.z;
            v_s[w][nq * 4 + 3][d] = ve.w;
        }
        __syncwarp();
#pragma unroll 8
        for (int n = 0; n < 32; n++) {
            float a[4], bb[8];
#pragma unroll
            for (int i = 0; i < 4; i++) a[i] = ek_s[w][n][ti * 4 + i];
#pragma unroll
            for (int j = 0; j < 8; j++) bb[j] = v_s[w][n][tj * 8 + j];
#pragma unroll
            for (int i = 0; i < 4; i++)
#pragma unroll
                for (int j = 0; j < 8; j++)
                    acc[i][j] = fmaf(a[i], bb[j], acc[i][j]);
        }
        __syncwarp();
    }

    const int stripe = chunk * 4 + w;    // 0..255
    float* out = g_ctx_part + ((long)(b * HEADS + h) * 256 + stripe) * (DH * DH);
#pragma unroll
    for (int i = 0; i < 4; i++)
#pragma unroll
        for (int j = 0; j < 8; j++)
            out[(ti * 4 + i) * DH + tj * 8 + j] = acc[i][j];
}

__global__ void ctx_reduce_kernel()
{
    int idx = blockIdx.x * blockDim.x + threadIdx.x;  // < B_*HEADS*1024
    int de = idx % (DH * DH);
    int bh = idx / (DH * DH);
    int d  = de / DH;
    int b  = bh / HEADS, h = bh % HEADS;
    const float* p = g_ctx_part + (long)bh * 256 * (DH * DH) + de;
    float s = 0.f;
#pragma unroll 8
    for (int st = 0; st < 256; st++) s += p[(long)st * (DH * DH)];
    float inv = 1.f / g_ksum[b * 256 + h * DH + d];
    g_ctx[(long)bh * (DH * DH) + de] = s * inv;
}

// ---------------------------------------------------------------------------
// Fold w_out with context; emit bf16 hi/lo W2.
// ---------------------------------------------------------------------------
__global__ void fold_w2_kernel(const float* __restrict__ w_out)
{
    int idx = blockIdx.x * blockDim.x + threadIdx.x;  // < B_*256*256
    int hd = idx % 256;
    int o  = (idx / 256) % 256;
    int b  = idx / 65536;
    int h = hd / DH, d = hd % DH;
    const float* wrow = w_out + o * 256 + h * DH;
    const float* ctx  = g_ctx + ((long)(b * HEADS + h) * DH + d) * DH;
    float s = 0.f;
#pragma unroll
    for (int e = 0; e < DH; e++) s = fmaf(wrow[e], ctx[e], s);
    __nv_bfloat16 hh = __float2bfloat16(s);
    g_w2h[(long)b * 65536 + o * 256 + hd] = hh;
    g_w2l[(long)b * 65536 + o * 256 + hd] = __float2bfloat16(s - __bfloat162float(hh));
}

// ---------------------------------------------------------------------------
// Launch
// ---------------------------------------------------------------------------
extern "C" void kernel_launch(void* const* d_in, const int* in_sizes, int n_in,
                              void* d_out, int out_size)
{
    const float* x     = (const float*)d_in[0];  // [2,256,32768]
    const float* w_qkv = (const float*)d_in[1];  // [768,256]
    const float* w_out = (const float*)d_in[2];  // [256,256]
    float* out = (float*)d_out;                  // [2,256,32768]

    float *qkv = nullptr;
    __nv_bfloat16 *qh, *ql, *wh, *wl, *w2h, *w2l;
    cudaGetSymbolAddress((void**)&qkv, g_qkv);
    cudaGetSymbolAddress((void**)&qh,  g_qh);
    cudaGetSymbolAddress((void**)&ql,  g_ql);
    cudaGetSymbolAddress((void**)&wh,  g_wh);
    cudaGetSymbolAddress((void**)&wl,  g_wl);
    cudaGetSymbolAddress((void**)&w2h, g_w2h);
    cudaGetSymbolAddress((void**)&w2l, g_w2l);

    cudaFuncSetAttribute(gemm_bf16split<1>, cudaFuncAttributeMaxDynamicSharedMemorySize, GEMM_SMEM);
    cudaFuncSetAttribute(gemm_bf16split<0>, cudaFuncAttributeMaxDynamicSharedMemorySize, GEMM_SMEM);

    // 0) bf16 hi/lo split of w_qkv only (x is converted inside GEMM1 now)
    cvt_split<<<(O1*CDIM/4 + 255)/256, 256>>>(w_qkv, wh, wl, (long)O1*CDIM);

    // 1) qkv = w_qkv @ x with fused fp32-B conversion + fused epilogues
    gemm_bf16split<1><<<dim3(NTOK/BN, O1/BM, B_), 256, GEMM_SMEM>>>(
        wh, wl, nullptr, nullptr, x, qkv, CDIM, NTOK,
        0L, (long)CDIM*NTOK, (long)O1*NTOK);

    // 2) finish k row sums
    ksum_reduce_kernel<<<B_ * 256, 256>>>();

    // 3) partial contexts
    ctx_part_kernel<<<dim3(64, HEADS, B_), 128>>>();

    // 4) reduce + normalize contexts
    ctx_reduce_kernel<<<(B_ * HEADS * DH * DH) / 256, 256>>>();

    // 5) fold output weight with context -> bf16 hi/lo
    fold_w2_kernel<<<(B_ * 256 * 256) / 256, 256>>>(w_out);

    // 6) out = W2 @ q  (bf16-pair B path, plain epilogue)
    gemm_bf16split<0><<<dim3(NTOK/BN, CDIM/BM, B_), 256, GEMM_SMEM>>>(
        w2h, w2l, qh, ql, nullptr, out, CDIM, NTOK,
        (long)CDIM*CDIM, (long)CDIM*NTOK, (long)CDIM*NTOK);
}